// round 6
// baseline (speedup 1.0000x reference)
#include <cuda_runtime.h>
#include <cstdint>

#define GG   128
#define AA   100
#define WIN  10
#define FDIM 16
#define HD   128
#define K1   (WIN*FDIM)   // 160
#define NN   (GG*AA)      // 12800

typedef unsigned long long ull;

// ---- packed f32x2 helpers ----
__device__ __forceinline__ ull pk2(float lo, float hi) {
    ull r; asm("mov.b64 %0, {%1,%2};" : "=l"(r) : "f"(lo), "f"(hi)); return r;
}
__device__ __forceinline__ ull fma2(ull a, ull b, ull c) {
    ull d; asm("fma.rn.f32x2 %0, %1, %2, %3;" : "=l"(d) : "l"(a), "l"(b), "l"(c)); return d;
}
__device__ __forceinline__ ull add2(ull a, ull b) {
    ull d; asm("add.rn.f32x2 %0, %1, %2;" : "=l"(d) : "l"(a), "l"(b)); return d;
}
__device__ __forceinline__ float2 upk2(ull v) {
    float lo, hi; asm("mov.b64 {%0,%1}, %2;" : "=f"(lo), "=f"(hi) : "l"(v));
    return make_float2(lo, hi);
}

// ---- gmem scratch ----
__device__ __align__(16) float g_h[(size_t)NN*HD];   // h3 for conv kernel

// ---------------------------------------------------------------------------
// Scheme A (cols packed, 2-D warp split 16 rowGroups x 2 colHalves):
// C[r][c-pair] = sum_k Adup[r][k] * B[k][c-pair].  A in dup-ull smem format
// (broadcast loads), B = W in gmem read as ull col-pairs. 64 cols per warp.
// ---------------------------------------------------------------------------
template<int KK, int R>
__device__ __forceinline__ void schemeA_tile(const ull* __restrict__ Ad, int start,
                                             const ull* __restrict__ B2,
                                             float* __restrict__ Pout,
                                             int ch, int lane)
{
    ull acc[R];
#pragma unroll
    for (int r = 0; r < R; r++) acc[r] = 0ull;

    const int cp = 32*ch + lane;   // col-pair index 0..63

#pragma unroll 2
    for (int j4 = 0; j4 < KK/4; j4++) {
        const ull b0 = B2[(4*j4+0)*64 + cp];
        const ull b1 = B2[(4*j4+1)*64 + cp];
        const ull b2 = B2[(4*j4+2)*64 + cp];
        const ull b3 = B2[(4*j4+3)*64 + cp];
#pragma unroll
        for (int r = 0; r < R; r++) {
            const ulonglong2* ap =
                reinterpret_cast<const ulonglong2*>(Ad + (size_t)(start+r)*KK + 4*j4);
            const ulonglong2 aA = ap[0];
            const ulonglong2 aB = ap[1];
            acc[r] = fma2(aA.x, b0, acc[r]);
            acc[r] = fma2(aA.y, b1, acc[r]);
            acc[r] = fma2(aB.x, b2, acc[r]);
            acc[r] = fma2(aB.y, b3, acc[r]);
        }
    }

    ull* sPu = reinterpret_cast<ull*>(Pout);
#pragma unroll
    for (int r = 0; r < R; r++) sPu[(size_t)(start+r)*64 + cp] = acc[r];
}

template<int KK>
__device__ __forceinline__ void schemeA_phase(const ull* __restrict__ Ad,
                                              const float* __restrict__ W,
                                              float* __restrict__ Pout,
                                              int rg, int ch, int lane)
{
    const ull* B2 = reinterpret_cast<const ull*>(W);
    if (rg < 4) schemeA_tile<KK, 7>(Ad, rg*7,          B2, Pout, ch, lane);
    else        schemeA_tile<KK, 6>(Ad, 28 + (rg-4)*6, B2, Pout, ch, lane);
}

// ---------------------------------------------------------------------------
// Scheme B (rows packed): C[(i0,i1)][c] = sum_k adj[i][k] * P[k][c].
// adj symmetric -> row-pair = contiguous broadcast ull. 64 cols per warp.
// ---------------------------------------------------------------------------
template<int PR, bool TOGMEM>
__device__ __forceinline__ void schemeB_tile(const float* __restrict__ s_adj,
                                             const float* __restrict__ s_P,
                                             const float* __restrict__ bias,
                                             int pairStart,
                                             ull* __restrict__ s_hd,
                                             float* __restrict__ gout,
                                             int ch, int lane)
{
    const int cbase = 64*ch + 2*lane;
    ull acc[PR][2];
#pragma unroll
    for (int p = 0; p < PR; p++) { acc[p][0] = 0ull; acc[p][1] = 0ull; }

#pragma unroll 2
    for (int k = 0; k < AA; k++) {
        const ull* ap = reinterpret_cast<const ull*>(s_adj + (size_t)k*AA);
        ull a[PR];
#pragma unroll
        for (int p = 0; p < PR; p++) a[p] = ap[pairStart + p];

        const float2 pv = *reinterpret_cast<const float2*>(s_P + (size_t)k*HD + cbase);
        const ull bd0 = pk2(pv.x, pv.x);
        const ull bd1 = pk2(pv.y, pv.y);
#pragma unroll
        for (int p = 0; p < PR; p++) {
            acc[p][0] = fma2(a[p], bd0, acc[p][0]);
            acc[p][1] = fma2(a[p], bd1, acc[p][1]);
        }
    }

    const float2 bb = *reinterpret_cast<const float2*>(bias + cbase);
#pragma unroll
    for (int p = 0; p < PR; p++) {
        const int i0 = 2*(pairStart + p), i1 = i0 + 1;
        const float2 v0 = upk2(acc[p][0]);   // (D[i0][c0], D[i1][c0])
        const float2 v1 = upk2(acc[p][1]);   // (D[i0][c1], D[i1][c1])
        const float r00 = fmaxf(v0.x + bb.x, 0.f);
        const float r01 = fmaxf(v1.x + bb.y, 0.f);
        const float r10 = fmaxf(v0.y + bb.x, 0.f);
        const float r11 = fmaxf(v1.y + bb.y, 0.f);
        if (TOGMEM) {
            *reinterpret_cast<float2*>(gout + (size_t)i0*HD + cbase) = make_float2(r00, r01);
            *reinterpret_cast<float2*>(gout + (size_t)i1*HD + cbase) = make_float2(r10, r11);
        } else {
            s_hd[(size_t)i0*HD + cbase    ] = pk2(r00, r00);
            s_hd[(size_t)i0*HD + cbase + 1] = pk2(r01, r01);
            s_hd[(size_t)i1*HD + cbase    ] = pk2(r10, r10);
            s_hd[(size_t)i1*HD + cbase + 1] = pk2(r11, r11);
        }
    }
}

template<bool TOGMEM>
__device__ __forceinline__ void schemeB_phase(const float* __restrict__ s_adj,
                                              const float* __restrict__ s_P,
                                              const float* __restrict__ bias,
                                              ull* __restrict__ s_hd,
                                              float* __restrict__ gout,
                                              int rg, int ch, int lane)
{
    // 50 row-pairs over 16 rowGroups: groups 0-1 -> 4 pairs, groups 2-15 -> 3.
    if (rg < 2) schemeB_tile<4, TOGMEM>(s_adj, s_P, bias, rg*4,          s_hd, gout, ch, lane);
    else        schemeB_tile<3, TOGMEM>(s_adj, s_P, bias, 8 + (rg-2)*3, s_hd, gout, ch, lane);
}

// ---------------------------------------------------------------------------
// Fused kernel: adjacency -> 6 GEMM phases. One block (1024 thr) per group.
// ---------------------------------------------------------------------------
__global__ void __launch_bounds__(1024, 1) fused_kernel(
    const float* __restrict__ x,
    const float* __restrict__ W1, const float* __restrict__ b1,
    const float* __restrict__ W2, const float* __restrict__ b2,
    const float* __restrict__ W3, const float* __restrict__ b3)
{
    extern __shared__ char sm[];
    ull*   s_hd  = reinterpret_cast<ull*>(sm);                       // 102400 B
    float* s_P   = reinterpret_cast<float*>(sm + (size_t)AA*HD*8);   // 51200 B
    float* s_adj = s_P + AA*HD;                                      // 40000 B

    __shared__ float xc[AA][WIN];
    __shared__ float invd[AA];
    __shared__ float dinv[AA];

    const int g    = blockIdx.x;
    const int tid  = threadIdx.x;
    const int warp = tid >> 5;
    const int lane = tid & 31;
    const int ch   = warp & 1;    // column half
    const int rg   = warp >> 1;   // row group 0..15

    // ---- Phase 0: adjacency ----
    if (tid < AA) {
        float r[WIN]; float s = 0.f;
#pragma unroll
        for (int t = 0; t < WIN; t++) {
            r[t] = x[((size_t)(g*AA + tid)*WIN + t)*FDIM + (FDIM-1)];
            s += r[t];
        }
        const float mean = s * (1.0f/WIN);
        float ss = 0.f;
#pragma unroll
        for (int t = 0; t < WIN; t++) {
            float v = r[t] - mean;
            xc[tid][t] = v;
            ss += v*v;
        }
        invd[tid] = rsqrtf(ss);
    }
    __syncthreads();

    if (tid < AA) {
        float xi[WIN];
#pragma unroll
        for (int t = 0; t < WIN; t++) xi[t] = xc[tid][t];
        const float di = invd[tid];
        float rs = 0.f;
#pragma unroll 2
        for (int j = 0; j < AA; j++) {
            float dot = 0.f;
#pragma unroll
            for (int t = 0; t < WIN; t++) dot = fmaf(xi[t], xc[j][t], dot);
            float c = dot * di * invd[j];
            rs += 1.0f - fabsf(c);
        }
        dinv[tid] = rsqrtf(rs + 1.0f);
    }
    __syncthreads();

    for (int e = tid; e < AA*AA; e += 1024) {
        const int i = e / AA, j = e - i*AA;
        float dot = 0.f;
#pragma unroll
        for (int t = 0; t < WIN; t++) dot = fmaf(xc[i][t], xc[j][t], dot);
        float c = dot * invd[i] * invd[j];
        float a = 1.0f - fabsf(c) + (i == j ? 1.0f : 0.0f);
        s_adj[e] = a * dinv[i] * dinv[j];
    }

    // ---- Phase 1: P = x@W1, K=160 split into two K=80 halves staged as
    //      dup-format x in s_hd (64000 B per half). Accumulators persist. ----
    {
        int start, R;
        if (rg < 4) { start = rg*7;          R = 7; }
        else        { start = 28 + (rg-4)*6; R = 6; }
        const int cp = 32*ch + lane;
        const ull* B2 = reinterpret_cast<const ull*>(W1);

        ull acc[7];
#pragma unroll
        for (int r = 0; r < 7; r++) acc[r] = 0ull;

#pragma unroll 1
        for (int h = 0; h < 2; h++) {
            __syncthreads();   // prior phase / prior half fully consumed
            const float* xh = x + (size_t)g*AA*K1 + 80*h;
            for (int idx = tid; idx < AA*80; idx += 1024) {
                const int row = idx / 80, kk = idx - row*80;
                const float v = xh[(size_t)row*K1 + kk];
                s_hd[idx] = pk2(v, v);
            }
            __syncthreads();

#pragma unroll 2
            for (int j4 = 0; j4 < 20; j4++) {
                const int kb = 80*h + 4*j4;
                const ull b0 = B2[(kb+0)*64 + cp];
                const ull b1 = B2[(kb+1)*64 + cp];
                const ull b2 = B2[(kb+2)*64 + cp];
                const ull b3 = B2[(kb+3)*64 + cp];
#pragma unroll
                for (int r = 0; r < 7; r++) {
                    if (r < R) {
                        const ulonglong2* ap = reinterpret_cast<const ulonglong2*>(
                            s_hd + (size_t)(start+r)*80 + 4*j4);
                        const ulonglong2 aA = ap[0];
                        const ulonglong2 aB = ap[1];
                        acc[r] = fma2(aA.x, b0, acc[r]);
                        acc[r] = fma2(aA.y, b1, acc[r]);
                        acc[r] = fma2(aB.x, b2, acc[r]);
                        acc[r] = fma2(aB.y, b3, acc[r]);
                    }
                }
            }
        }

        ull* sPu = reinterpret_cast<ull*>(s_P);
#pragma unroll
        for (int r = 0; r < 7; r++)
            if (r < R) sPu[(size_t)(start+r)*64 + cp] = acc[r];
    }
    __syncthreads();

    // ---- Phase 2: h1 = relu(adj@P + b1) -> s_hd (dup) ----
    schemeB_phase<false>(s_adj, s_P, b1, s_hd, nullptr, rg, ch, lane);
    __syncthreads();
    // ---- Phase 3: P = h1@W2 ----
    schemeA_phase<HD>(s_hd, W2, s_P, rg, ch, lane);
    __syncthreads();
    // ---- Phase 4: h2 = relu(adj@P + b2) -> s_hd (dup) ----
    schemeB_phase<false>(s_adj, s_P, b2, s_hd, nullptr, rg, ch, lane);
    __syncthreads();
    // ---- Phase 5: P = h2@W3 ----
    schemeA_phase<HD>(s_hd, W3, s_P, rg, ch, lane);
    __syncthreads();
    // ---- Phase 6: h3 = relu(adj@P + b3) -> gmem ----
    schemeB_phase<true>(s_adj, s_P, b3, nullptr, g_h + (size_t)g*AA*HD, rg, ch, lane);
}

// ---------------------------------------------------------------------------
// Conv kernel: fused conv1(relu)+conv2, one warp per row, full-chip grid.
// ---------------------------------------------------------------------------
__global__ void __launch_bounds__(256) conv_kernel(
    const float* __restrict__ cw1, const float* __restrict__ cb1,
    const float* __restrict__ cw2, const float* __restrict__ cb2,
    float* __restrict__ out)
{
    __shared__ ulonglong2 wpk[HD][4];

    const int tid = threadIdx.x;
    if (tid < HD) {
        const float wx = cw1[3*tid+0], wy = cw1[3*tid+1], wz = cw1[3*tid+2];
        const float wb = cb1[tid];
        const float u0 = 0.5f*cw2[3*tid+0], u1 = 0.5f*cw2[3*tid+1], u2 = 0.5f*cw2[3*tid+2];
        wpk[tid][0] = make_ulonglong2(pk2(wx, wx), pk2(wy, wy));
        wpk[tid][1] = make_ulonglong2(pk2(wz, wz), pk2(wb, wb));
        wpk[tid][2] = make_ulonglong2(pk2(u0, u0), pk2(u1, u1));
        wpk[tid][3] = make_ulonglong2(pk2(u2, u2), 0ull);
    }
    __syncthreads();

    const int warp = tid >> 5, lane = tid & 31;
    const int row  = blockIdx.x*8 + warp;

    const float4 hv = reinterpret_cast<const float4*>(g_h + (size_t)row*HD)[lane];
    float hm1 = __shfl_up_sync(0xffffffffu, hv.w, 1);  if (lane == 0)  hm1 = 0.f;
    float hp1 = __shfl_down_sync(0xffffffffu, hv.x, 1); if (lane == 31) hp1 = 0.f;

    const ull Pm = pk2(hm1,  hv.x);
    const ull P0 = pk2(hv.x, hv.y);
    const ull P1 = pk2(hv.y, hv.z);
    const ull P2 = pk2(hv.z, hv.w);
    const ull P3 = pk2(hv.w, hp1);

    const ull M = 0x7FFFFFFF7FFFFFFFull;

    ull T0a = 0ull, T0b = 0ull, T1a = 0ull, T1b = 0ull, T2a = 0ull, T2b = 0ull;

#pragma unroll 4
    for (int c = 0; c < HD; c++) {
        const ulonglong2 q0 = wpk[c][0];
        const ulonglong2 q1 = wpk[c][1];
        const ulonglong2 q2 = wpk[c][2];
        const ull        q3 = wpk[c][3].x;

        ull z01 = fma2(q0.x, Pm, fma2(q0.y, P0, fma2(q1.x, P1, q1.y)));
        ull z23 = fma2(q0.x, P1, fma2(q0.y, P2, fma2(q1.x, P3, q1.y)));

        z01 = add2(z01, z01 & M);   // 2*relu(z); 0.5 folded into u-weights
        z23 = add2(z23, z23 & M);

        T0a = fma2(q2.x, z01, T0a);  T0b = fma2(q2.x, z23, T0b);
        T1a = fma2(q2.y, z01, T1a);  T1b = fma2(q2.y, z23, T1b);
        T2a = fma2(q3,   z01, T2a);  T2b = fma2(q3,   z23, T2b);
    }

    const float2 t0a = upk2(T0a), t0b = upk2(T0b);
    const float2 t1a = upk2(T1a), t1b = upk2(T1b);
    const float2 t2a = upk2(T2a), t2b = upk2(T2b);

    float t0m = __shfl_up_sync(0xffffffffu, t0b.y, 1);  if (lane == 0)  t0m = 0.f;
    float t2p = __shfl_down_sync(0xffffffffu, t2a.x, 1); if (lane == 31) t2p = 0.f;

    const float c2 = cb2[0];
    float4 res;
    res.x = t0m   + t1a.x + t2a.y + c2;
    res.y = t0a.x + t1a.y + t2b.x + c2;
    res.z = t0a.y + t1b.x + t2b.y + c2;
    res.w = t0b.x + t1b.y + t2p   + c2;
    reinterpret_cast<float4*>(out + (size_t)row*HD)[lane] = res;
}

// ---------------------------------------------------------------------------
extern "C" void kernel_launch(void* const* d_in, const int* in_sizes, int n_in,
                              void* d_out, int out_size)
{
    const float* x   = (const float*)d_in[0];
    const float* W1  = (const float*)d_in[1];
    const float* b1  = (const float*)d_in[2];
    const float* W2  = (const float*)d_in[3];
    const float* b2  = (const float*)d_in[4];
    const float* W3  = (const float*)d_in[5];
    const float* b3  = (const float*)d_in[6];
    const float* cw1 = (const float*)d_in[7];
    const float* cb1 = (const float*)d_in[8];
    const float* cw2 = (const float*)d_in[9];
    const float* cb2 = (const float*)d_in[10];
    float* out = (float*)d_out;

    const int SMEM = AA*HD*8 + AA*HD*4 + AA*AA*4;   // 193600 B
    cudaFuncSetAttribute(fused_kernel, cudaFuncAttributeMaxDynamicSharedMemorySize, SMEM);

    fused_kernel<<<GG, 1024, SMEM>>>(x, W1, b1, W2, b2, W3, b3);

    conv_kernel<<<NN/8, 256>>>(cw1, cb1, cw2, cb2, out);
}

// round 8
// speedup vs baseline: 1.2990x; 1.2990x over previous
#include <cuda_runtime.h>
#include <cuda_bf16.h>
#include <cstdint>

#define GG   128
#define AA   100
#define WIN  10
#define FDIM 16
#define HD   128
#define K1   (WIN*FDIM)   // 160
#define NN   (GG*AA)

typedef unsigned long long ull;

// ===== f32x2 helpers (conv kernel) =====
__device__ __forceinline__ ull pk2(float lo, float hi) {
    ull r; asm("mov.b64 %0, {%1,%2};" : "=l"(r) : "f"(lo), "f"(hi)); return r;
}
__device__ __forceinline__ ull fma2(ull a, ull b, ull c) {
    ull d; asm("fma.rn.f32x2 %0, %1, %2, %3;" : "=l"(d) : "l"(a), "l"(b), "l"(c)); return d;
}
__device__ __forceinline__ ull add2(ull a, ull b) {
    ull d; asm("add.rn.f32x2 %0, %1, %2;" : "=l"(d) : "l"(a), "l"(b)); return d;
}
__device__ __forceinline__ float2 upk2(ull v) {
    float lo, hi; asm("mov.b64 {%0,%1}, %2;" : "=f"(lo), "=f"(hi) : "l"(v));
    return make_float2(lo, hi);
}

// ===== mma/ldmatrix helpers (sm_80-level PTX, safe on compute_103) =====
__device__ __forceinline__ uint32_t smem_u32(const void* p) {
    uint32_t a; asm("{ .reg .u64 t; cvta.to.shared.u64 t, %1; cvt.u32.u64 %0, t; }"
                    : "=r"(a) : "l"(p)); return a;
}
__device__ __forceinline__ void ldsm4(uint32_t addr, uint32_t r[4]) {
    asm volatile("ldmatrix.sync.aligned.m8n8.x4.shared.b16 {%0,%1,%2,%3}, [%4];"
        : "=r"(r[0]), "=r"(r[1]), "=r"(r[2]), "=r"(r[3]) : "r"(addr));
}
__device__ __forceinline__ void mma16816(float* c, const uint32_t a[4],
                                         uint32_t b0, uint32_t b1) {
    asm volatile("mma.sync.aligned.m16n8k16.row.col.f32.bf16.bf16.f32 "
        "{%0,%1,%2,%3}, {%4,%5,%6,%7}, {%8,%9}, {%0,%1,%2,%3};"
        : "+f"(c[0]), "+f"(c[1]), "+f"(c[2]), "+f"(c[3])
        : "r"(a[0]), "r"(a[1]), "r"(a[2]), "r"(a[3]), "r"(b0), "r"(b1));
}
__device__ __forceinline__ void splitf(float v, float& vh, float& vl) {
    vh = __bfloat162float(__float2bfloat16(v)); vl = v - vh;
}
__device__ __forceinline__ void st_bf(char* base, uint32_t off, float v) {
    *reinterpret_cast<__nv_bfloat16*>(base + off) = __float2bfloat16(v);
}
__device__ __forceinline__ uint32_t pkbf(float a, float b) {
    __nv_bfloat162 t = __floats2bfloat162_rn(a, b);
    return *reinterpret_cast<uint32_t*>(&t);
}

// strides (bytes): A/Bt rows = 128+8 bf16 pad = 272B; adj rows = 112+8 = 240B
#define SA 272
#define SJ 240

__device__ __align__(16) float g_h[(size_t)NN*HD];

// ---------------------------------------------------------------------------
// Warp GEMM: D(16 rows x 128 cols) += A(16xK) @ B(KxN), bf16 3-term split.
// A: [m][k] row-major bf16 (hi/lo), B stored transposed Bt: [n][k] (hi/lo).
// ---------------------------------------------------------------------------
template<int KS, int STRA>
__device__ __forceinline__ void gemm_mma(const char* aH, const char* aL,
                                         const char* bH, const char* bL,
                                         float (&acc)[16][4], int lane, int m0)
{
    const uint32_t aHu = smem_u32(aH), aLu = smem_u32(aL);
    const uint32_t bHu = smem_u32(bH), bLu = smem_u32(bL);
    const uint32_t offA = (uint32_t)(m0 + (lane & 15))*STRA + ((lane >> 4) << 4);
    const uint32_t offB = (uint32_t)(((lane >> 4) << 3) + (lane & 7))*SA
                        + (((lane >> 3) & 1) << 4);
#pragma unroll
    for (int ks = 0; ks < KS; ks++) {
        uint32_t ah[4], al[4];
        ldsm4(aHu + offA + ks*32, ah);
        ldsm4(aLu + offA + ks*32, al);
#pragma unroll
        for (int np = 0; np < 8; np++) {
            uint32_t bh[4], bl[4];
            ldsm4(bHu + offB + np*(16*SA) + ks*32, bh);
            ldsm4(bLu + offB + np*(16*SA) + ks*32, bl);
            mma16816(acc[2*np],   ah, bh[0], bh[1]);
            mma16816(acc[2*np],   al, bh[0], bh[1]);
            mma16816(acc[2*np],   ah, bl[0], bl[1]);
            mma16816(acc[2*np+1], ah, bh[2], bh[3]);
            mma16816(acc[2*np+1], al, bh[2], bh[3]);
            mma16816(acc[2*np+1], ah, bl[2], bl[3]);
        }
    }
}

__device__ __forceinline__ void zero_acc(float (&acc)[16][4]) {
#pragma unroll
    for (int i = 0; i < 16; i++)
#pragma unroll
        for (int j = 0; j < 4; j++) acc[i][j] = 0.f;
}

// Epilogue: D -> Bt layout (Bt[n][k=row]) split hi/lo; rows >= AA -> 0.
__device__ __forceinline__ void epi_T(float (&acc)[16][4], char* bH, char* bL,
                                      int lane, int m0)
{
    const int r0 = m0 + (lane >> 2), r1 = r0 + 8;
    const int nb = 2*(lane & 3);
#pragma unroll
    for (int nt = 0; nt < 16; nt++) {
        const int n0 = 8*nt + nb;
        const float c0 = (r0 < AA) ? acc[nt][0] : 0.f;
        const float c1 = (r0 < AA) ? acc[nt][1] : 0.f;
        const float c2 = (r1 < AA) ? acc[nt][2] : 0.f;
        const float c3 = (r1 < AA) ? acc[nt][3] : 0.f;
        float h, l;
        splitf(c0, h, l); st_bf(bH, n0*SA     + r0*2, h); st_bf(bL, n0*SA     + r0*2, l);
        splitf(c1, h, l); st_bf(bH, (n0+1)*SA + r0*2, h); st_bf(bL, (n0+1)*SA + r0*2, l);
        splitf(c2, h, l); st_bf(bH, n0*SA     + r1*2, h); st_bf(bL, n0*SA     + r1*2, l);
        splitf(c3, h, l); st_bf(bH, (n0+1)*SA + r1*2, h); st_bf(bL, (n0+1)*SA + r1*2, l);
    }
}

// Epilogue: H = relu(D + bias) -> A layout (hi/lo) or fp32 gmem.
template<bool TOGMEM>
__device__ __forceinline__ void epi_A(float (&acc)[16][4], const float* __restrict__ bias,
                                      char* aH, char* aL, float* __restrict__ gout,
                                      int lane, int m0)
{
    const int r0 = m0 + (lane >> 2), r1 = r0 + 8;
    const int nb = 2*(lane & 3);
#pragma unroll
    for (int nt = 0; nt < 16; nt++) {
        const int n0 = 8*nt + nb;
        const float b0 = bias[n0], b1 = bias[n0+1];
        float v00 = fmaxf(acc[nt][0] + b0, 0.f);
        float v01 = fmaxf(acc[nt][1] + b1, 0.f);
        float v10 = fmaxf(acc[nt][2] + b0, 0.f);
        float v11 = fmaxf(acc[nt][3] + b1, 0.f);
        if (TOGMEM) {
            if (r0 < AA) *reinterpret_cast<float2*>(gout + (size_t)r0*HD + n0) = make_float2(v00, v01);
            if (r1 < AA) *reinterpret_cast<float2*>(gout + (size_t)r1*HD + n0) = make_float2(v10, v11);
        } else {
            if (r0 >= AA) { v00 = 0.f; v01 = 0.f; }
            if (r1 >= AA) { v10 = 0.f; v11 = 0.f; }
            float h0, l0, h1, l1;
            splitf(v00, h0, l0); splitf(v01, h1, l1);
            *reinterpret_cast<uint32_t*>(aH + r0*SA + n0*2) = pkbf(h0, h1);
            *reinterpret_cast<uint32_t*>(aL + r0*SA + n0*2) = pkbf(l0, l1);
            splitf(v10, h0, l0); splitf(v11, h1, l1);
            *reinterpret_cast<uint32_t*>(aH + r1*SA + n0*2) = pkbf(h0, h1);
            *reinterpret_cast<uint32_t*>(aL + r1*SA + n0*2) = pkbf(l0, l1);
        }
    }
}

// Stage W^T (K x 128 gmem, row-major) into Bt[n][k] hi/lo.
__device__ __forceinline__ void stageW(const float* __restrict__ W, int K,
                                       char* bH, char* bL, int tid)
{
    for (int idx = tid; idx < K*128; idx += 256) {
        const int k = idx >> 7, n = idx & 127;
        float vh, vl; splitf(W[idx], vh, vl);
        const uint32_t o = (uint32_t)n*SA + k*2;
        st_bf(bH, o, vh); st_bf(bL, o, vl);
    }
}

// ---------------------------------------------------------------------------
__global__ void __launch_bounds__(256, 1) gcn_kernel(
    const float* __restrict__ x,
    const float* __restrict__ W1, const float* __restrict__ b1,
    const float* __restrict__ W2, const float* __restrict__ b2,
    const float* __restrict__ W3, const float* __restrict__ b3)
{
    extern __shared__ char smd[];
    char* sAh = smd;               // 128*272 = 34816
    char* sAl = smd + 34816;
    char* sBh = smd + 69632;
    char* sBl = smd + 104448;
    char* sJh = smd + 139264;      // 128*240 = 30720
    char* sJl = smd + 169984;      // end 200704

    __shared__ float xc[AA][WIN];
    __shared__ float invd[AA], dinv[AA];

    const int g    = blockIdx.x;
    const int tid  = threadIdx.x;
    const int warp = tid >> 5;
    const int lane = tid & 31;
    const int m0   = warp * 16;

    // ---- adjacency prerequisites ----
    if (tid < AA) {
        float r[WIN]; float s = 0.f;
#pragma unroll
        for (int t = 0; t < WIN; t++) {
            r[t] = x[((size_t)(g*AA + tid)*WIN + t)*FDIM + (FDIM-1)]; s += r[t];
        }
        const float mean = s * (1.0f/WIN); float ss = 0.f;
#pragma unroll
        for (int t = 0; t < WIN; t++) { float v = r[t]-mean; xc[tid][t] = v; ss += v*v; }
        invd[tid] = rsqrtf(ss);
    }
    __syncthreads();
    if (tid < AA) {
        float xi[WIN];
#pragma unroll
        for (int t = 0; t < WIN; t++) xi[t] = xc[tid][t];
        const float di = invd[tid]; float rs = 0.f;
        for (int j = 0; j < AA; j++) {
            float dot = 0.f;
#pragma unroll
            for (int t = 0; t < WIN; t++) dot = fmaf(xi[t], xc[j][t], dot);
            rs += 1.0f - fabsf(dot * di * invd[j]);
        }
        dinv[tid] = rsqrtf(rs + 1.0f);
    }
    __syncthreads();

    // ---- stage adj (bf16 hi/lo, A-layout, 128x112 padded with zeros) ----
    for (int e = tid; e < 128*112; e += 256) {
        const int i = e / 112, j = e - i*112;
        float a = 0.f;
        if (i < AA && j < AA) {
            float dot = 0.f;
#pragma unroll
            for (int t = 0; t < WIN; t++) dot = fmaf(xc[i][t], xc[j][t], dot);
            float c = dot * invd[i] * invd[j];
            a = (1.0f - fabsf(c) + (i == j ? 1.0f : 0.0f)) * dinv[i] * dinv[j];
        }
        float vh, vl; splitf(a, vh, vl);
        const uint32_t o = (uint32_t)i*SJ + j*2;
        st_bf(sJh, o, vh); st_bf(sJl, o, vl);
    }

    float acc[16][4];
    zero_acc(acc);

    // ---- GEMM1: P1 = x @ W1 (K=160, two K=80 chunks) ----
#pragma unroll 1
    for (int c = 0; c < 2; c++) {
        __syncthreads();   // prior readers done
        for (int idx = tid; idx < 128*80; idx += 256) {
            const int r = idx / 80, k = idx - r*80;
            float v = (r < AA) ? x[((size_t)(g*AA + r))*K1 + 80*c + k] : 0.f;
            float vh, vl; splitf(v, vh, vl);
            const uint32_t o = (uint32_t)r*SA + k*2;
            st_bf(sAh, o, vh); st_bf(sAl, o, vl);
        }
        stageW(W1 + (size_t)80*c*128, 80, sBh, sBl, tid);
        __syncthreads();
        gemm_mma<5, SA>(sAh, sAl, sBh, sBl, acc, lane, m0);
    }
    __syncthreads();
    epi_T(acc, sBh, sBl, lane, m0);            // P1^T -> Bt
    __syncthreads();

    // ---- GEMM2: H1 = relu(adj @ P1 + b1) ----
    zero_acc(acc);
    gemm_mma<7, SJ>(sJh, sJl, sBh, sBl, acc, lane, m0);
    __syncthreads();
    epi_A<false>(acc, b1, sAh, sAl, nullptr, lane, m0);
    stageW(W2, HD, sBh, sBl, tid);
    __syncthreads();

    // ---- GEMM3: P2 = H1 @ W2 ----
    zero_acc(acc);
    gemm_mma<8, SA>(sAh, sAl, sBh, sBl, acc, lane, m0);
    __syncthreads();
    epi_T(acc, sBh, sBl, lane, m0);
    __syncthreads();

    // ---- GEMM4: H2 = relu(adj @ P2 + b2) ----
    zero_acc(acc);
    gemm_mma<7, SJ>(sJh, sJl, sBh, sBl, acc, lane, m0);
    __syncthreads();
    epi_A<false>(acc, b2, sAh, sAl, nullptr, lane, m0);
    stageW(W3, HD, sBh, sBl, tid);
    __syncthreads();

    // ---- GEMM5: P3 = H2 @ W3 ----
    zero_acc(acc);
    gemm_mma<8, SA>(sAh, sAl, sBh, sBl, acc, lane, m0);
    __syncthreads();
    epi_T(acc, sBh, sBl, lane, m0);
    __syncthreads();

    // ---- GEMM6: h3 = relu(adj @ P3 + b3) -> gmem ----
    zero_acc(acc);
    gemm_mma<7, SJ>(sJh, sJl, sBh, sBl, acc, lane, m0);
    epi_A<true>(acc, b3, nullptr, nullptr, g_h + (size_t)g*AA*HD, lane, m0);
}

// ---------------------------------------------------------------------------
// conv1(relu)+conv2 fused, one warp per row (fp32 roofline-bound)
// ---------------------------------------------------------------------------
__global__ void __launch_bounds__(256) conv_kernel(
    const float* __restrict__ cw1, const float* __restrict__ cb1,
    const float* __restrict__ cw2, const float* __restrict__ cb2,
    float* __restrict__ out)
{
    __shared__ ulonglong2 wpk[HD][4];
    const int tid = threadIdx.x;
    if (tid < HD) {
        const float wx = cw1[3*tid+0], wy = cw1[3*tid+1], wz = cw1[3*tid+2];
        const float wb = cb1[tid];
        const float u0 = 0.5f*cw2[3*tid+0], u1 = 0.5f*cw2[3*tid+1], u2 = 0.5f*cw2[3*tid+2];
        wpk[tid][0] = make_ulonglong2(pk2(wx, wx), pk2(wy, wy));
        wpk[tid][1] = make_ulonglong2(pk2(wz, wz), pk2(wb, wb));
        wpk[tid][2] = make_ulonglong2(pk2(u0, u0), pk2(u1, u1));
        wpk[tid][3] = make_ulonglong2(pk2(u2, u2), 0ull);
    }
    __syncthreads();

    const int warp = tid >> 5, lane = tid & 31;
    const int row  = blockIdx.x*8 + warp;

    const float4 hv = reinterpret_cast<const float4*>(g_h + (size_t)row*HD)[lane];
    float hm1 = __shfl_up_sync(0xffffffffu, hv.w, 1);  if (lane == 0)  hm1 = 0.f;
    float hp1 = __shfl_down_sync(0xffffffffu, hv.x, 1); if (lane == 31) hp1 = 0.f;

    const ull Pm = pk2(hm1,  hv.x);
    const ull P0 = pk2(hv.x, hv.y);
    const ull P1 = pk2(hv.y, hv.z);
    const ull P2 = pk2(hv.z, hv.w);
    const ull P3 = pk2(hv.w, hp1);
    const ull M = 0x7FFFFFFF7FFFFFFFull;

    ull T0a=0, T0b=0, T1a=0, T1b=0, T2a=0, T2b=0;
#pragma unroll 4
    for (int c = 0; c < HD; c++) {
        const ulonglong2 q0 = wpk[c][0];
        const ulonglong2 q1 = wpk[c][1];
        const ulonglong2 q2 = wpk[c][2];
        const ull        q3 = wpk[c][3].x;
        ull z01 = fma2(q0.x, Pm, fma2(q0.y, P0, fma2(q1.x, P1, q1.y)));
        ull z23 = fma2(q0.x, P1, fma2(q0.y, P2, fma2(q1.x, P3, q1.y)));
        z01 = add2(z01, z01 & M);
        z23 = add2(z23, z23 & M);
        T0a = fma2(q2.x, z01, T0a);  T0b = fma2(q2.x, z23, T0b);
        T1a = fma2(q2.y, z01, T1a);  T1b = fma2(q2.y, z23, T1b);
        T2a = fma2(q3,   z01, T2a);  T2b = fma2(q3,   z23, T2b);
    }
    const float2 t0a = upk2(T0a), t0b = upk2(T0b);
    const float2 t1a = upk2(T1a), t1b = upk2(T1b);
    const float2 t2a = upk2(T2a), t2b = upk2(T2b);

    float t0m = __shfl_up_sync(0xffffffffu, t0b.y, 1);  if (lane == 0)  t0m = 0.f;
    float t2p = __shfl_down_sync(0xffffffffu, t2a.x, 1); if (lane == 31) t2p = 0.f;

    const float c2 = cb2[0];
    float4 res;
    res.x = t0m   + t1a.x + t2a.y + c2;
    res.y = t0a.x + t1a.y + t2b.x + c2;
    res.z = t0a.y + t1b.x + t2b.y + c2;
    res.w = t0b.x + t1b.y + t2p   + c2;
    reinterpret_cast<float4*>(out + (size_t)row*HD)[lane] = res;
}

// ---------------------------------------------------------------------------
extern "C" void kernel_launch(void* const* d_in, const int* in_sizes, int n_in,
                              void* d_out, int out_size)
{
    const float* x   = (const float*)d_in[0];
    const float* W1  = (const float*)d_in[1];
    const float* b1  = (const float*)d_in[2];
    const float* W2  = (const float*)d_in[3];
    const float* b2  = (const float*)d_in[4];
    const float* W3  = (const float*)d_in[5];
    const float* b3  = (const float*)d_in[6];
    const float* cw1 = (const float*)d_in[7];
    const float* cb1 = (const float*)d_in[8];
    const float* cw2 = (const float*)d_in[9];
    const float* cb2 = (const float*)d_in[10];
    float* out = (float*)d_out;

    const int SMEM = 200704;
    cudaFuncSetAttribute(gcn_kernel, cudaFuncAttributeMaxDynamicSharedMemorySize, SMEM);

    gcn_kernel<<<GG, 256, SMEM>>>(x, W1, b1, W2, b2, W3, b3);
    conv_kernel<<<NN/8, 256>>>(cw1, cb1, cw2, cb2, out);
}